// round 4
// baseline (speedup 1.0000x reference)
#include <cuda_runtime.h>

// Problem constants
#define TT 64   // timesteps == layers
#define BB 128  // batch
#define HH 64   // hidden
#define NG 256  // 4*H gate width

// Persistent device state (allowed: __device__ globals, no allocation)
__device__ float g_hbuf[2][TT][BB][HH];  // h double-buffered by t parity
__device__ float g_c[TT][BB][HH];        // cell state per layer
__device__ float g_outs[BB][TT][HH];     // top-layer h per timestep

__device__ __forceinline__ float sigf(float x) {
    return 1.0f / (1.0f + __expf(-x));
}
__device__ __forceinline__ float tanh_(float x) {
    // tanh(x) = 2*sigmoid(2x) - 1 ; __expf accurate to ~1e-6 rel, saturates correctly
    return 2.0f / (1.0f + __expf(-2.0f * x)) - 1.0f;
}

// ---------------------------------------------------------------------------
// Zero the recurrent state (h parity buffers + c). g_outs is fully overwritten.
// ---------------------------------------------------------------------------
__global__ void zero_state_kernel() {
    unsigned i = blockIdx.x * blockDim.x + threadIdx.x;
    unsigned stride = gridDim.x * blockDim.x;
    const float4 z = make_float4(0.f, 0.f, 0.f, 0.f);
    float4* a = reinterpret_cast<float4*>(&g_hbuf[0][0][0][0]);
    unsigned na = sizeof(g_hbuf) / 16;
    for (unsigned k = i; k < na; k += stride) a[k] = z;
    float4* b = reinterpret_cast<float4*>(&g_c[0][0][0]);
    unsigned nb = sizeof(g_c) / 16;
    for (unsigned k = i; k < nb; k += stride) b[k] = z;
}

// ---------------------------------------------------------------------------
// One wavefront w (cells with l + t == w).
// grid.y = cell index within wavefront, grid.x = batch chunk (M = 8*MR rows).
// Thread (tm, tn): rows m0 + tm*MR + [0..MR), h-columns {2*tn, 2*tn+1} for all
// 4 gates -> gate epilogue is thread-local.
// GEMM: z[M,256] = Xin[M,64] @ Wx[64,256] + Hprev[M,64] @ Wh[64,256] + bias
// (layer 0: Xin is the scalar x[b,t], handled directly from global.)
// ---------------------------------------------------------------------------
template <int MR>
__global__ __launch_bounds__(256)
void lstm_wave_kernel(int w,
                      const float* __restrict__ x,
                      const float* __restrict__ W0,
                      const float* __restrict__ b0,
                      const float* __restrict__ Wl,
                      const float* __restrict__ bl) {
    constexpr int M = 8 * MR;
    const int lo = (w > TT - 1) ? (w - (TT - 1)) : 0;
    const int l  = lo + blockIdx.y;
    const int t  = w - l;
    const int m0 = blockIdx.x * M;

    const int tid = threadIdx.x;
    const int tn = tid & 31;   // column pair selector
    const int tm = tid >> 5;   // row group (== warp id)

    __shared__ float As[16][M + 1];  // +1 pad: conflict-free strided writes
    __shared__ float Ws[16][NG];

    // accumulators: acc[row][gate][col in {2tn, 2tn+1}]
    float acc[MR][4][2];
    const float* bias = (l == 0) ? b0 : (bl + (size_t)(l - 1) * NG);
#pragma unroll
    for (int g = 0; g < 4; ++g) {
        float2 bv = *reinterpret_cast<const float2*>(bias + g * 64 + 2 * tn);
#pragma unroll
        for (int r = 0; r < MR; ++r) { acc[r][g][0] = bv.x; acc[r][g][1] = bv.y; }
    }

    // Layer 0: scalar-x contribution (W0 row 0)
    if (l == 0) {
        float xv[MR];
#pragma unroll
        for (int r = 0; r < MR; ++r)
            xv[r] = x[(size_t)(m0 + tm * MR + r) * TT + t];
#pragma unroll
        for (int g = 0; g < 4; ++g) {
            float2 wv = *reinterpret_cast<const float2*>(W0 + g * 64 + 2 * tn);
#pragma unroll
            for (int r = 0; r < MR; ++r) {
                acc[r][g][0] += xv[r] * wv.x;
                acc[r][g][1] += xv[r] * wv.y;
            }
        }
    }

    // Two K=64 halves: half0 = input-h (layer below, time t), half1 = own h(t-1)
    for (int half = 0; half < 2; ++half) {
        const float* Asrc;
        const float* Wsrc;
        if (half == 0) {
            if (l == 0) continue;  // uniform per CTA, no divergence
            Asrc = &g_hbuf[t & 1][l - 1][m0][0];
            Wsrc = Wl + (size_t)(l - 1) * 128 * NG;
        } else {
            Asrc = &g_hbuf[(t & 1) ^ 1][l][m0][0];
            Wsrc = (l == 0) ? (W0 + NG)
                            : (Wl + (size_t)(l - 1) * 128 * NG + (size_t)64 * NG);
        }

        for (int k0 = 0; k0 < 64; k0 += 16) {
            __syncthreads();
            // Load A tile (16 x M), transposed into As[k][m]
            constexpr int AEL = 16 * M;
#pragma unroll
            for (int i = 0; i < (AEL + 255) / 256; ++i) {
                int e = tid + i * 256;
                if (e < AEL) {
                    int kk = e & 15, m = e >> 4;
                    As[kk][m] = Asrc[(size_t)m * HH + k0 + kk];
                }
            }
            // Load W tile (16 x 256) as float4
#pragma unroll
            for (int i = 0; i < 4; ++i) {
                int e4 = tid + i * 256;
                int kk = e4 >> 6, n4 = (e4 & 63) * 4;
                *reinterpret_cast<float4*>(&Ws[kk][n4]) =
                    *reinterpret_cast<const float4*>(Wsrc + (size_t)(k0 + kk) * NG + n4);
            }
            __syncthreads();

#pragma unroll
            for (int kk = 0; kk < 16; ++kk) {
                float a[MR];
#pragma unroll
                for (int r = 0; r < MR; ++r) a[r] = As[kk][tm * MR + r];  // warp-uniform (broadcast)
#pragma unroll
                for (int g = 0; g < 4; ++g) {
                    float2 wv = *reinterpret_cast<const float2*>(&Ws[kk][g * 64 + 2 * tn]);
#pragma unroll
                    for (int r = 0; r < MR; ++r) {
                        acc[r][g][0] += a[r] * wv.x;
                        acc[r][g][1] += a[r] * wv.y;
                    }
                }
            }
        }
    }

    // Gate epilogue (thread-local; gate order i, j, f, o)
#pragma unroll
    for (int r = 0; r < MR; ++r) {
        const int b = m0 + tm * MR + r;
        float2 cold = *reinterpret_cast<float2*>(&g_c[l][b][2 * tn]);
        float2 c2, h2;
        {
            float gi = sigf(acc[r][0][0]);
            float gj = tanh_(acc[r][1][0]);
            float gf = sigf(acc[r][2][0]);
            float go = sigf(acc[r][3][0]);
            c2.x = cold.x * gf + gi * gj;
            h2.x = tanh_(c2.x) * go;
        }
        {
            float gi = sigf(acc[r][0][1]);
            float gj = tanh_(acc[r][1][1]);
            float gf = sigf(acc[r][2][1]);
            float go = sigf(acc[r][3][1]);
            c2.y = cold.y * gf + gi * gj;
            h2.y = tanh_(c2.y) * go;
        }
        *reinterpret_cast<float2*>(&g_c[l][b][2 * tn]) = c2;
        *reinterpret_cast<float2*>(&g_hbuf[t & 1][l][b][2 * tn]) = h2;
        if (l == TT - 1)
            *reinterpret_cast<float2*>(&g_outs[b][t][2 * tn]) = h2;
    }
}

// ---------------------------------------------------------------------------
// Per-timestep dense(1) + ReLU: pred[b,t] = relu(outs[b,t,:] . Wd[t,:] + bd[t])
// ---------------------------------------------------------------------------
__global__ void dense_kernel(const float* __restrict__ Wd,
                             const float* __restrict__ bd,
                             float* __restrict__ out) {
    int idx = blockIdx.x * blockDim.x + threadIdx.x;  // 0..8191 == b*64 + t
    if (idx >= BB * TT) return;
    int b = idx >> 6, t = idx & 63;
    const float4* o  = reinterpret_cast<const float4*>(&g_outs[b][t][0]);
    const float4* wv = reinterpret_cast<const float4*>(Wd + (size_t)t * HH);
    float s = bd[t];
#pragma unroll
    for (int h4 = 0; h4 < HH / 4; ++h4) {
        float4 ov = o[h4], w4 = wv[h4];
        s += ov.x * w4.x + ov.y * w4.y + ov.z * w4.z + ov.w * w4.w;
    }
    out[idx] = fmaxf(s, 0.0f);
}

// ---------------------------------------------------------------------------
// loss = mean((labels - pred)^2) ; single CTA, deterministic reduction
// ---------------------------------------------------------------------------
__global__ void loss_kernel(const float* __restrict__ labels,
                            float* __restrict__ out, int out_size) {
    __shared__ float red[1024];
    int tid = threadIdx.x;
    float s = 0.0f;
    for (int i = tid; i < BB * TT; i += 1024) {
        float d = labels[i] - out[i];
        s += d * d;
    }
    red[tid] = s;
    __syncthreads();
    for (int off = 512; off > 0; off >>= 1) {
        if (tid < off) red[tid] += red[tid + off];
        __syncthreads();
    }
    if (tid == 0 && out_size > BB * TT)
        out[BB * TT] = red[0] / (float)(BB * TT);
}

// ---------------------------------------------------------------------------
// kernel_launch: zero state, 127 wavefront launches, dense + loss.
// Graph-capturable: kernel launches only.
// ---------------------------------------------------------------------------
extern "C" void kernel_launch(void* const* d_in, const int* in_sizes, int n_in,
                              void* d_out, int out_size) {
    const float* x      = (const float*)d_in[0];  // [B, T, 1]
    const float* labels = (const float*)d_in[1];  // [B, T, 1]
    const float* W0     = (const float*)d_in[2];  // [65, 256]
    const float* b0     = (const float*)d_in[3];  // [256]
    const float* Wl     = (const float*)d_in[4];  // [63, 128, 256]
    const float* bl     = (const float*)d_in[5];  // [63, 256]
    const float* Wd     = (const float*)d_in[6];  // [64, 64, 1]
    const float* bd     = (const float*)d_in[7];  // [64, 1]
    float* out = (float*)d_out;

    zero_state_kernel<<<1024, 256>>>();

    for (int w = 0; w < 2 * TT - 1; ++w) {
        int lo = (w > TT - 1) ? (w - (TT - 1)) : 0;
        int hi = (w < TT - 1) ? w : (TT - 1);
        int width = hi - lo + 1;
        if (width >= 32) {
            // M=32, 4 batch chunks -> up to 256 CTAs
            lstm_wave_kernel<4><<<dim3(4, width), 256>>>(w, x, W0, b0, Wl, bl);
        } else if (width >= 16) {
            // M=16, 8 batch chunks
            lstm_wave_kernel<2><<<dim3(8, width), 256>>>(w, x, W0, b0, Wl, bl);
        } else {
            // M=8, 16 batch chunks -> keep narrow wavefronts latency-short
            lstm_wave_kernel<1><<<dim3(16, width), 256>>>(w, x, W0, b0, Wl, bl);
        }
    }

    dense_kernel<<<(BB * TT + 255) / 256, 256>>>(Wd, bd, out);
    loss_kernel<<<1, 1024>>>(labels, out, out_size);
}

// round 5
// speedup vs baseline: 1.0816x; 1.0816x over previous
#include <cuda_runtime.h>

// Problem constants
#define TT 64   // timesteps == layers
#define BB 128  // batch
#define HH 64   // hidden
#define NG 256  // 4*H gate width

// Persistent device state
__device__ float g_hbuf[2][TT][BB][HH];  // h double-buffered by t parity
__device__ float g_c[TT][BB][HH];        // cell state per layer
__device__ float g_outs[BB][TT][HH];     // top-layer h per timestep

__device__ __forceinline__ float sigf(float x) {
    return 1.0f / (1.0f + __expf(-x));
}
__device__ __forceinline__ float tanh_(float x) {
    return 2.0f / (1.0f + __expf(-2.0f * x)) - 1.0f;
}

// ---- packed f32x2 helpers (FFMA2 path; bit-exact vs 2x scalar FFMA) ----
__device__ __forceinline__ unsigned long long pk2(float v) {
    unsigned long long r;
    asm("mov.b64 %0, {%1, %1};" : "=l"(r) : "r"(__float_as_uint(v)));
    return r;
}
__device__ __forceinline__ unsigned long long pack2(float lo, float hi) {
    unsigned long long r;
    asm("mov.b64 %0, {%1, %2};" : "=l"(r)
        : "r"(__float_as_uint(lo)), "r"(__float_as_uint(hi)));
    return r;
}
__device__ __forceinline__ void fma2(unsigned long long& d,
                                     unsigned long long a, unsigned long long b) {
    asm("fma.rn.f32x2 %0, %1, %2, %0;" : "+l"(d) : "l"(a), "l"(b));
}
__device__ __forceinline__ float2 upk(unsigned long long v) {
    unsigned lo, hi;
    asm("mov.b64 {%0, %1}, %2;" : "=r"(lo), "=r"(hi) : "l"(v));
    return make_float2(__uint_as_float(lo), __uint_as_float(hi));
}

// ---------------------------------------------------------------------------
__global__ void zero_state_kernel() {
    unsigned i = blockIdx.x * blockDim.x + threadIdx.x;
    unsigned stride = gridDim.x * blockDim.x;
    const float4 z = make_float4(0.f, 0.f, 0.f, 0.f);
    float4* a = reinterpret_cast<float4*>(&g_hbuf[0][0][0][0]);
    unsigned na = sizeof(g_hbuf) / 16;
    for (unsigned k = i; k < na; k += stride) a[k] = z;
    float4* b = reinterpret_cast<float4*>(&g_c[0][0][0]);
    unsigned nb = sizeof(g_c) / 16;
    for (unsigned k = i; k < nb; k += stride) b[k] = z;
}

// ---------------------------------------------------------------------------
// One wavefront w (cells with l + t == w). grid.y = cell, grid.x = batch chunk.
// M = 8*MR rows/CTA; thread (tm warp, tn lane) owns rows tm*MR+[0..MR), col
// pair {2tn, 2tn+1} in all 4 gates (thread-local LSTM epilogue).
// Unified K=128 GEMM (K<64: h from layer below at t; K>=64: own h at t-1),
// FFMA2 inner product, cp.async double-buffered W tiles, A fully staged in smem.
// ---------------------------------------------------------------------------
template <int MR>
__global__ __launch_bounds__(256)
void lstm_wave_kernel(int w,
                      const float* __restrict__ x,
                      const float* __restrict__ W0,
                      const float* __restrict__ b0,
                      const float* __restrict__ Wl,
                      const float* __restrict__ bl) {
    constexpr int M = 8 * MR;
    // A stride: MR>=4 needs 16B-aligned float4 rows (stride%4==0); %32==12 -> 4-way STS
    constexpr int ASTR = (MR >= 4) ? (M + 12) : (M + 1);
    extern __shared__ float sm[];
    float* As = sm;                     // [128][ASTR] (k-major, transposed A)
    float* Ws = sm + 128 * ASTR;        // [2][16][256] double-buffered W tiles

    const int lo = (w > TT - 1) ? (w - (TT - 1)) : 0;
    const int l  = lo + blockIdx.y;
    const int t  = w - l;
    const int m0 = blockIdx.x * M;

    const int tid = threadIdx.x;
    const int tn = tid & 31;
    const int tm = tid >> 5;

    // Unified weight base: row k (0..127) -> Wbase + k*NG
    const float* Wbase = (l == 0) ? (W0 - 63 * NG)
                                  : (Wl + (size_t)(l - 1) * 128 * NG);
    const float* bias = (l == 0) ? b0 : (bl + (size_t)(l - 1) * NG);
    const int s0 = (l == 0) ? 4 : 0;    // k-tiles of 16 rows; layer 0 has K=64

    unsigned ws_base = (unsigned)__cvta_generic_to_shared(Ws);

    // --- prefetch W tile s0 into buffer 0 (cp.async, 16B granules) ---
    {
        const float* gW = Wbase + (size_t)s0 * 16 * NG;
#pragma unroll
        for (int i = 0; i < 4; ++i) {
            int idx = tid + i * 256;                // 0..1023 float4s
            int row = idx >> 6, c4 = (idx & 63) << 2;
            unsigned dst = ws_base + (unsigned)((row << 8) + c4) * 4u;
            const float* src = gW + row * NG + c4;
            asm volatile("cp.async.cg.shared.global [%0], [%1], 16;\n"
                         :: "r"(dst), "l"(src));
        }
        asm volatile("cp.async.commit_group;\n");
    }

    // --- stage A into smem (transposed, k-major) while W tile is in flight ---
    const float* hown = &g_hbuf[(t & 1) ^ 1][l][m0][0];
    if (l == 0) {
        for (int e = tid; e < 64 * M; e += 256) {
            int m = e >> 6, k = e & 63;             // coalesced over k
            As[(64 + k) * ASTR + m] = hown[m * HH + k];
        }
    } else {
        const float* hbelow = &g_hbuf[t & 1][l - 1][m0][0];
        for (int e = tid; e < 128 * M; e += 256) {
            int m = e >> 7, k = e & 127;            // coalesced over k
            float v = (k < 64) ? hbelow[m * HH + k] : hown[m * HH + (k - 64)];
            As[k * ASTR + m] = v;
        }
    }

    // --- init accumulators with bias (packed col pairs) ---
    unsigned long long acc[MR][4];
#pragma unroll
    for (int g = 0; g < 4; ++g) {
        float2 bv = *reinterpret_cast<const float2*>(bias + g * 64 + 2 * tn);
        unsigned long long p = pack2(bv.x, bv.y);
#pragma unroll
        for (int r = 0; r < MR; ++r) acc[r][g] = p;
    }

    // --- layer 0: scalar x contribution (W0 row 0) ---
    if (l == 0) {
#pragma unroll
        for (int r = 0; r < MR; ++r) {
            float xv = x[(size_t)(m0 + tm * MR + r) * TT + t];
            unsigned long long x2 = pk2(xv);
#pragma unroll
            for (int g = 0; g < 4; ++g) {
                float2 wv = *reinterpret_cast<const float2*>(W0 + g * 64 + 2 * tn);
                fma2(acc[r][g], x2, pack2(wv.x, wv.y));
            }
        }
    }

    // --- main k-tile loop (double-buffered W pipeline) ---
    for (int s = s0; s < 8; ++s) {
        if (s + 1 < 8) {
            const float* gW = Wbase + (size_t)(s + 1) * 16 * NG;
            unsigned bofs = ((unsigned)((s + 1) & 1)) * 4096u * 4u;
#pragma unroll
            for (int i = 0; i < 4; ++i) {
                int idx = tid + i * 256;
                int row = idx >> 6, c4 = (idx & 63) << 2;
                unsigned dst = ws_base + bofs + (unsigned)((row << 8) + c4) * 4u;
                const float* src = gW + row * NG + c4;
                asm volatile("cp.async.cg.shared.global [%0], [%1], 16;\n"
                             :: "r"(dst), "l"(src));
            }
            asm volatile("cp.async.commit_group;\n");
            asm volatile("cp.async.wait_group 1;\n");
        } else {
            asm volatile("cp.async.wait_group 0;\n");
        }
        __syncthreads();

        const float* wsb = Ws + (s & 1) * 4096;
        const float* asb = As + (s * 16) * ASTR;
#pragma unroll
        for (int kk = 0; kk < 16; ++kk) {
            const float* arow = asb + kk * ASTR + tm * MR;
            unsigned long long a2[MR];
            if constexpr (MR >= 4) {
#pragma unroll
                for (int q = 0; q < MR / 4; ++q) {
                    float4 av = *reinterpret_cast<const float4*>(arow + 4 * q);
                    a2[4 * q + 0] = pk2(av.x);
                    a2[4 * q + 1] = pk2(av.y);
                    a2[4 * q + 2] = pk2(av.z);
                    a2[4 * q + 3] = pk2(av.w);
                }
            } else {
#pragma unroll
                for (int r = 0; r < MR; ++r) a2[r] = pk2(arow[r]);
            }
            const float* wrow = wsb + kk * 256 + 2 * tn;
#pragma unroll
            for (int g = 0; g < 4; ++g) {
                unsigned long long w2 =
                    *reinterpret_cast<const unsigned long long*>(wrow + g * 64);
#pragma unroll
                for (int r = 0; r < MR; ++r) fma2(acc[r][g], a2[r], w2);
            }
        }
        __syncthreads();
    }

    // --- LSTM gate epilogue (gate order i, j, f, o) ---
#pragma unroll
    for (int r = 0; r < MR; ++r) {
        const int b = m0 + tm * MR + r;
        float2 zi = upk(acc[r][0]);
        float2 zj = upk(acc[r][1]);
        float2 zf = upk(acc[r][2]);
        float2 zo = upk(acc[r][3]);
        float2 cold = *reinterpret_cast<float2*>(&g_c[l][b][2 * tn]);
        float2 c2, h2;
        c2.x = cold.x * sigf(zf.x) + sigf(zi.x) * tanh_(zj.x);
        h2.x = tanh_(c2.x) * sigf(zo.x);
        c2.y = cold.y * sigf(zf.y) + sigf(zi.y) * tanh_(zj.y);
        h2.y = tanh_(c2.y) * sigf(zo.y);
        *reinterpret_cast<float2*>(&g_c[l][b][2 * tn]) = c2;
        *reinterpret_cast<float2*>(&g_hbuf[t & 1][l][b][2 * tn]) = h2;
        if (l == TT - 1)
            *reinterpret_cast<float2*>(&g_outs[b][t][2 * tn]) = h2;
    }
}

// ---------------------------------------------------------------------------
__global__ void dense_kernel(const float* __restrict__ Wd,
                             const float* __restrict__ bd,
                             float* __restrict__ out) {
    int idx = blockIdx.x * blockDim.x + threadIdx.x;  // b*64 + t
    if (idx >= BB * TT) return;
    int b = idx >> 6, t = idx & 63;
    const float4* o  = reinterpret_cast<const float4*>(&g_outs[b][t][0]);
    const float4* wv = reinterpret_cast<const float4*>(Wd + (size_t)t * HH);
    float s = bd[t];
#pragma unroll
    for (int h4 = 0; h4 < HH / 4; ++h4) {
        float4 ov = o[h4], w4 = wv[h4];
        s += ov.x * w4.x + ov.y * w4.y + ov.z * w4.z + ov.w * w4.w;
    }
    out[idx] = fmaxf(s, 0.0f);
}

__global__ void loss_kernel(const float* __restrict__ labels,
                            float* __restrict__ out, int out_size) {
    __shared__ float red[1024];
    int tid = threadIdx.x;
    float s = 0.0f;
    for (int i = tid; i < BB * TT; i += 1024) {
        float d = labels[i] - out[i];
        s += d * d;
    }
    red[tid] = s;
    __syncthreads();
    for (int off = 512; off > 0; off >>= 1) {
        if (tid < off) red[tid] += red[tid + off];
        __syncthreads();
    }
    if (tid == 0 && out_size > BB * TT)
        out[BB * TT] = red[0] / (float)(BB * TT);
}

// ---------------------------------------------------------------------------
static inline int smem_bytes(int MR) {
    int M = 8 * MR;
    int astr = (MR >= 4) ? (M + 12) : (M + 1);
    return (128 * astr + 2 * 16 * 256) * 4;
}

extern "C" void kernel_launch(void* const* d_in, const int* in_sizes, int n_in,
                              void* d_out, int out_size) {
    const float* x      = (const float*)d_in[0];
    const float* labels = (const float*)d_in[1];
    const float* W0     = (const float*)d_in[2];
    const float* b0     = (const float*)d_in[3];
    const float* Wl     = (const float*)d_in[4];
    const float* bl     = (const float*)d_in[5];
    const float* Wd     = (const float*)d_in[6];
    const float* bd     = (const float*)d_in[7];
    float* out = (float*)d_out;

    // Allow >48KB dynamic smem for the big tiles (idempotent, not an allocation)
    cudaFuncSetAttribute(lstm_wave_kernel<8>,
                         cudaFuncAttributeMaxDynamicSharedMemorySize, smem_bytes(8));
    cudaFuncSetAttribute(lstm_wave_kernel<4>,
                         cudaFuncAttributeMaxDynamicSharedMemorySize, smem_bytes(4));

    zero_state_kernel<<<1024, 256>>>();

    for (int w = 0; w < 2 * TT - 1; ++w) {
        int lo = (w > TT - 1) ? (w - (TT - 1)) : 0;
        int hi = (w < TT - 1) ? w : (TT - 1);
        int width = hi - lo + 1;
        if (width >= 48) {
            lstm_wave_kernel<8><<<dim3(2, width), 256, smem_bytes(8)>>>(w, x, W0, b0, Wl, bl);
        } else if (width >= 24) {
            lstm_wave_kernel<4><<<dim3(4, width), 256, smem_bytes(4)>>>(w, x, W0, b0, Wl, bl);
        } else if (width >= 12) {
            lstm_wave_kernel<2><<<dim3(8, width), 256, smem_bytes(2)>>>(w, x, W0, b0, Wl, bl);
        } else {
            lstm_wave_kernel<1><<<dim3(16, width), 256, smem_bytes(1)>>>(w, x, W0, b0, Wl, bl);
        }
    }

    dense_kernel<<<(BB * TT + 255) / 256, 256>>>(Wd, bd, out);
    loss_kernel<<<1, 1024>>>(labels, out, out_size);
}